// round 6
// baseline (speedup 1.0000x reference)
#include <cuda_runtime.h>
#include <cuda_bf16.h>
#include <cstdint>

// Problem constants (shapes fixed by reference setup_inputs)
#define D_IN_C   4096
#define R_C      64
#define KSEL_C   16
#define TEMP_C   0.1f
#define SCALE_C  (16.0f / 16.0f)

#define MAX_M    8192

// Scratch (allocation-free: device globals)
__device__ float g_z[MAX_M * R_C];
__device__ float g_zs[MAX_M * R_C];

// ---------------------------------------------------------------------------
// Helpers
// ---------------------------------------------------------------------------
__device__ __forceinline__ uint32_t f2tf32(float f) {
    uint32_t r;
    asm("cvt.rna.tf32.f32 %0, %1;" : "=r"(r) : "f"(f));
    return r;
}

__device__ __forceinline__ void mma_tf32(float* d, const uint32_t* a, const uint32_t* b) {
    asm volatile(
        "mma.sync.aligned.m16n8k8.row.col.f32.tf32.tf32.f32 "
        "{%0,%1,%2,%3},{%4,%5,%6,%7},{%8,%9},{%0,%1,%2,%3};"
        : "+f"(d[0]), "+f"(d[1]), "+f"(d[2]), "+f"(d[3])
        : "r"(a[0]), "r"(a[1]), "r"(a[2]), "r"(a[3]), "r"(b[0]), "r"(b[1]));
}

__device__ __forceinline__ void cp_async16(float* dst_smem, const float* src_gmem) {
    uint32_t s = (uint32_t)__cvta_generic_to_shared(dst_smem);
    asm volatile("cp.async.cg.shared.global [%0], [%1], 16;\n" :: "r"(s), "l"(src_gmem));
}

// ---------------------------------------------------------------------------
// TF32 GEMM:  out[m][n] = sum_k X[m][k] * Wt[n][k]  (+ LoRA K-extension + bias)
//
// BM=128, BK=32, 128 threads = 4 warps arranged 2(m) x 2(n).
// Warp tile: 64 x (BN/2).  m16n8k8 tiles: MT=4, NT=BN/16.
// Smem pitch 36 floats: fragment quad loads map to 32 distinct banks.
// ---------------------------------------------------------------------------
#define BM_G    128
#define BK_G    32
#define PITCH_G 36

template<int BN, bool FUSE_LORA, bool ADD_BIAS>
__global__ void __launch_bounds__(128)
gemm_tf32(const float* __restrict__ X,  int ldx,
          const float* __restrict__ Wt, int ldw,
          const float* __restrict__ ZS,   // [M][R_C]  (only if FUSE_LORA)
          const float* __restrict__ BL,   // [N][R_C]  (only if FUSE_LORA)
          const float* __restrict__ bias,
          float* __restrict__ out, int ldo,
          int KT_main, int KT_total)
{
    constexpr int NT = BN / 16;       // n8 tiles per warp (WARPS_N = 2)
    extern __shared__ float smem[];
    float* As = smem;                          // [2][BM_G][PITCH_G]
    float* Bs = smem + 2 * BM_G * PITCH_G;     // [2][BN][PITCH_G]

    const int tid  = threadIdx.x;
    const int lane = tid & 31;
    const int wid  = tid >> 5;
    const int wm   = wid >> 1;     // 0..1
    const int wn   = wid & 1;      // 0..1

    const int bm = blockIdx.y * BM_G;
    const int bn = blockIdx.x * BN;

    float acc[4][NT][4];
#pragma unroll
    for (int mt = 0; mt < 4; mt++)
#pragma unroll
        for (int nt = 0; nt < NT; nt++)
#pragma unroll
            for (int i = 0; i < 4; i++) acc[mt][nt][i] = 0.0f;

    auto issue_copy = [&](int kb, int stage) {
        float* as = As + stage * BM_G * PITCH_G;
        float* bs = Bs + stage * BN * PITCH_G;
        const bool main_k = (!FUSE_LORA) || (kb < KT_main);
        // A tile: BM_G x BK_G -> (BM_G*BK_G/4) float4, 128 threads
#pragma unroll
        for (int i = 0; i < (BM_G * BK_G) / (4 * 128); i++) {
            int linear = tid + i * 128;
            int row = linear >> 3;             // 8 float4 per 32-float row
            int cv  = (linear & 7) << 2;
            const float* src = main_k
                ? X  + (size_t)(bm + row) * ldx + (size_t)kb * BK_G + cv
                : ZS + (size_t)(bm + row) * R_C + (size_t)(kb - KT_main) * BK_G + cv;
            cp_async16(&as[row * PITCH_G + cv], src);
        }
        // B tile: BN x BK_G
#pragma unroll
        for (int i = 0; i < (BN * BK_G) / (4 * 128); i++) {
            int linear = tid + i * 128;
            int row = linear >> 3;
            int cv  = (linear & 7) << 2;
            const float* src = main_k
                ? Wt + (size_t)(bn + row) * ldw + (size_t)kb * BK_G + cv
                : BL + (size_t)(bn + row) * R_C + (size_t)(kb - KT_main) * BK_G + cv;
            cp_async16(&bs[row * PITCH_G + cv], src);
        }
        asm volatile("cp.async.commit_group;\n" ::: "memory");
    };

    issue_copy(0, 0);

    for (int kb = 0; kb < KT_total; kb++) {
        const int stage = kb & 1;
        if (kb + 1 < KT_total) {
            issue_copy(kb + 1, (kb + 1) & 1);
            asm volatile("cp.async.wait_group 1;\n" ::: "memory");
        } else {
            asm volatile("cp.async.wait_group 0;\n" ::: "memory");
        }
        __syncthreads();

        const float* as = As + stage * BM_G * PITCH_G + (wm * 64) * PITCH_G;
        const float* bs = Bs + stage * BN * PITCH_G + (wn * (BN / 2)) * PITCH_G;

#pragma unroll
        for (int kk = 0; kk < BK_G / 8; kk++) {
            uint32_t afrag[4][4];
#pragma unroll
            for (int mt = 0; mt < 4; mt++) {
                int r = mt * 16 + (lane >> 2);
                int c = kk * 8 + (lane & 3);
                afrag[mt][0] = f2tf32(as[r * PITCH_G + c]);
                afrag[mt][1] = f2tf32(as[(r + 8) * PITCH_G + c]);
                afrag[mt][2] = f2tf32(as[r * PITCH_G + c + 4]);
                afrag[mt][3] = f2tf32(as[(r + 8) * PITCH_G + c + 4]);
            }
            uint32_t bfrag[NT][2];
#pragma unroll
            for (int nt = 0; nt < NT; nt++) {
                int n = nt * 8 + (lane >> 2);
                int c = kk * 8 + (lane & 3);
                bfrag[nt][0] = f2tf32(bs[n * PITCH_G + c]);
                bfrag[nt][1] = f2tf32(bs[n * PITCH_G + c + 4]);
            }
#pragma unroll
            for (int mt = 0; mt < 4; mt++)
#pragma unroll
                for (int nt = 0; nt < NT; nt++)
                    mma_tf32(acc[mt][nt], afrag[mt], bfrag[nt]);
        }
        __syncthreads();
    }

    // Epilogue
#pragma unroll
    for (int mt = 0; mt < 4; mt++) {
#pragma unroll
        for (int nt = 0; nt < NT; nt++) {
            int r0 = bm + wm * 64 + mt * 16 + (lane >> 2);
            int c0 = bn + wn * (BN / 2) + nt * 8 + (lane & 3) * 2;
            float b0 = 0.0f, b1 = 0.0f;
            if (ADD_BIAS) { b0 = __ldg(&bias[c0]); b1 = __ldg(&bias[c0 + 1]); }
            float2 v0 = make_float2(acc[mt][nt][0] + b0, acc[mt][nt][1] + b1);
            float2 v1 = make_float2(acc[mt][nt][2] + b0, acc[mt][nt][3] + b1);
            *(float2*)&out[(size_t)r0 * ldo + c0]       = v0;
            *(float2*)&out[(size_t)(r0 + 8) * ldo + c0] = v1;
        }
    }
}

// ---------------------------------------------------------------------------
// Soft top-k mask: one warp per row of 64 z values.
// Exact 16th-largest |z| (counting duplicates) via 16 max-extractions,
// then z_sparse = z * sigmoid((|z|-thr)/TEMP) * SCALE.
// ---------------------------------------------------------------------------
__global__ void topk_mask_kernel(const float* __restrict__ z,
                                 float* __restrict__ zs, int M)
{
    const int row  = blockIdx.x * 8 + (threadIdx.x >> 5);
    const int lane = threadIdx.x & 31;
    if (row >= M) return;

    float z0 = z[row * R_C + lane];
    float z1 = z[row * R_C + lane + 32];
    float v0 = fabsf(z0), v1 = fabsf(z1);
    bool alive0 = true, alive1 = true;
    float thr = 0.0f;

#pragma unroll 1
    for (int it = 0; it < KSEL_C; it++) {
        float m = fmaxf(alive0 ? v0 : -1.0f, alive1 ? v1 : -1.0f);
#pragma unroll
        for (int off = 16; off; off >>= 1)
            m = fmaxf(m, __shfl_xor_sync(0xffffffffu, m, off));
        thr = m;
        unsigned b = __ballot_sync(0xffffffffu, alive0 && v0 == m);
        if (b) {
            if (lane == (__ffs(b) - 1)) alive0 = false;
        } else {
            unsigned b2 = __ballot_sync(0xffffffffu, alive1 && v1 == m);
            if (lane == (__ffs(b2) - 1)) alive1 = false;
        }
    }

    const float inv_t = 1.0f / TEMP_C;
    float m0 = 1.0f / (1.0f + expf(-(v0 - thr) * inv_t));
    float m1 = 1.0f / (1.0f + expf(-(v1 - thr) * inv_t));
    zs[row * R_C + lane]      = z0 * m0 * SCALE_C;
    zs[row * R_C + lane + 32] = z1 * m1 * SCALE_C;
}

// ---------------------------------------------------------------------------
// Launch
// ---------------------------------------------------------------------------
extern "C" void kernel_launch(void* const* d_in, const int* in_sizes, int n_in,
                              void* d_out, int out_size)
{
    const float* x    = (const float*)d_in[0];   // [M][4096]
    const float* Amat = (const float*)d_in[1];   // [64][4096]
    const float* Bmat = (const float*)d_in[2];   // [4096][64]
    const float* Wmat = (const float*)d_in[3];   // [4096][4096]
    const float* bias = (const float*)d_in[4];   // [4096]
    float* out = (float*)d_out;

    const int M = in_sizes[0] / D_IN_C;          // 8192
    const int N = in_sizes[4];                   // 4096

    float *z_ptr = nullptr, *zs_ptr = nullptr;
    cudaGetSymbolAddress((void**)&z_ptr,  g_z);
    cudaGetSymbolAddress((void**)&zs_ptr, g_zs);

    const int smem_z    = 2 * (BM_G + 64)  * PITCH_G * 4;   // 55296 B
    const int smem_main = 2 * (BM_G + 128) * PITCH_G * 4;   // 73728 B
    cudaFuncSetAttribute(gemm_tf32<64,  false, false>,
                         cudaFuncAttributeMaxDynamicSharedMemorySize, smem_z);
    cudaFuncSetAttribute(gemm_tf32<128, true,  true>,
                         cudaFuncAttributeMaxDynamicSharedMemorySize, smem_main);

    // 1) z = x @ A^T   (M x 64, K = 4096)
    {
        dim3 grid(64 / 64, M / BM_G);
        gemm_tf32<64, false, false><<<grid, 128, smem_z>>>(
            x, D_IN_C, Amat, D_IN_C,
            nullptr, nullptr, nullptr,
            z_ptr, R_C,
            D_IN_C / BK_G, D_IN_C / BK_G);
    }

    // 2) soft top-k mask -> z_sparse (scaled)
    topk_mask_kernel<<<M / 8, 256>>>(z_ptr, zs_ptr, M);

    // 3) out = x @ W^T + bias + z_sparse @ B^T   (K-extension fusion: 4096 + 64)
    {
        dim3 grid(N / 128, M / BM_G);
        gemm_tf32<128, true, true><<<grid, 128, smem_main>>>(
            x, D_IN_C, Wmat, D_IN_C,
            zs_ptr, Bmat, bias,
            out, N,
            D_IN_C / BK_G, D_IN_C / BK_G + R_C / BK_G);
    }
}

// round 7
// speedup vs baseline: 1.0013x; 1.0013x over previous
#include <cuda_runtime.h>
#include <cuda_bf16.h>
#include <cstdint>

// Problem constants (shapes fixed by reference setup_inputs)
#define D_IN_C   4096
#define R_C      64
#define KSEL_C   16
#define TEMP_C   0.1f
#define SCALE_C  (16.0f / 16.0f)

#define MAX_M    8192

// Scratch (allocation-free: device globals)
__device__ float g_z[MAX_M * R_C];
__device__ float g_zs[MAX_M * R_C];

// ---------------------------------------------------------------------------
// Helpers
// ---------------------------------------------------------------------------
__device__ __forceinline__ uint32_t f2tf32(float f) {
    uint32_t r;
    asm("cvt.rna.tf32.f32 %0, %1;" : "=r"(r) : "f"(f));
    return r;
}

__device__ __forceinline__ void mma_tf32(float* d, const uint32_t* a, const uint32_t* b) {
    asm volatile(
        "mma.sync.aligned.m16n8k8.row.col.f32.tf32.tf32.f32 "
        "{%0,%1,%2,%3},{%4,%5,%6,%7},{%8,%9},{%0,%1,%2,%3};"
        : "+f"(d[0]), "+f"(d[1]), "+f"(d[2]), "+f"(d[3])
        : "r"(a[0]), "r"(a[1]), "r"(a[2]), "r"(a[3]), "r"(b[0]), "r"(b[1]));
}

__device__ __forceinline__ void cp_async16(float* dst_smem, const float* src_gmem) {
    uint32_t s = (uint32_t)__cvta_generic_to_shared(dst_smem);
    asm volatile("cp.async.cg.shared.global [%0], [%1], 16;\n" :: "r"(s), "l"(src_gmem));
}

// ---------------------------------------------------------------------------
// TF32 GEMM:  out[m][n] = sum_k X[m][k] * Wt[n][k]  (+ LoRA K-extension + bias)
//
// BM=128, BK=32, 128 threads = 4 warps arranged 2(m) x 2(n).
// Warp tile: 64 x (BN/2).  m16n8k8 tiles: MT=4, NT=BN/16.
// Smem pitch 36 floats: fragment quad loads map to 32 distinct banks.
// ---------------------------------------------------------------------------
#define BM_G    128
#define BK_G    32
#define PITCH_G 36

template<int BN, bool FUSE_LORA, bool ADD_BIAS>
__global__ void __launch_bounds__(128)
gemm_tf32(const float* __restrict__ X,  int ldx,
          const float* __restrict__ Wt, int ldw,
          const float* __restrict__ ZS,   // [M][R_C]  (only if FUSE_LORA)
          const float* __restrict__ BL,   // [N][R_C]  (only if FUSE_LORA)
          const float* __restrict__ bias,
          float* __restrict__ out, int ldo,
          int KT_main, int KT_total)
{
    constexpr int NT = BN / 16;       // n8 tiles per warp (WARPS_N = 2)
    extern __shared__ float smem[];
    float* As = smem;                          // [2][BM_G][PITCH_G]
    float* Bs = smem + 2 * BM_G * PITCH_G;     // [2][BN][PITCH_G]

    const int tid  = threadIdx.x;
    const int lane = tid & 31;
    const int wid  = tid >> 5;
    const int wm   = wid >> 1;     // 0..1
    const int wn   = wid & 1;      // 0..1

    const int bm = blockIdx.y * BM_G;
    const int bn = blockIdx.x * BN;

    float acc[4][NT][4];
#pragma unroll
    for (int mt = 0; mt < 4; mt++)
#pragma unroll
        for (int nt = 0; nt < NT; nt++)
#pragma unroll
            for (int i = 0; i < 4; i++) acc[mt][nt][i] = 0.0f;

    auto issue_copy = [&](int kb, int stage) {
        float* as = As + stage * BM_G * PITCH_G;
        float* bs = Bs + stage * BN * PITCH_G;
        const bool main_k = (!FUSE_LORA) || (kb < KT_main);
        // A tile: BM_G x BK_G -> (BM_G*BK_G/4) float4, 128 threads
#pragma unroll
        for (int i = 0; i < (BM_G * BK_G) / (4 * 128); i++) {
            int linear = tid + i * 128;
            int row = linear >> 3;             // 8 float4 per 32-float row
            int cv  = (linear & 7) << 2;
            const float* src = main_k
                ? X  + (size_t)(bm + row) * ldx + (size_t)kb * BK_G + cv
                : ZS + (size_t)(bm + row) * R_C + (size_t)(kb - KT_main) * BK_G + cv;
            cp_async16(&as[row * PITCH_G + cv], src);
        }
        // B tile: BN x BK_G
#pragma unroll
        for (int i = 0; i < (BN * BK_G) / (4 * 128); i++) {
            int linear = tid + i * 128;
            int row = linear >> 3;
            int cv  = (linear & 7) << 2;
            const float* src = main_k
                ? Wt + (size_t)(bn + row) * ldw + (size_t)kb * BK_G + cv
                : BL + (size_t)(bn + row) * R_C + (size_t)(kb - KT_main) * BK_G + cv;
            cp_async16(&bs[row * PITCH_G + cv], src);
        }
        asm volatile("cp.async.commit_group;\n" ::: "memory");
    };

    issue_copy(0, 0);

    for (int kb = 0; kb < KT_total; kb++) {
        const int stage = kb & 1;
        if (kb + 1 < KT_total) {
            issue_copy(kb + 1, (kb + 1) & 1);
            asm volatile("cp.async.wait_group 1;\n" ::: "memory");
        } else {
            asm volatile("cp.async.wait_group 0;\n" ::: "memory");
        }
        __syncthreads();

        const float* as = As + stage * BM_G * PITCH_G + (wm * 64) * PITCH_G;
        const float* bs = Bs + stage * BN * PITCH_G + (wn * (BN / 2)) * PITCH_G;

#pragma unroll
        for (int kk = 0; kk < BK_G / 8; kk++) {
            uint32_t afrag[4][4];
#pragma unroll
            for (int mt = 0; mt < 4; mt++) {
                int r = mt * 16 + (lane >> 2);
                int c = kk * 8 + (lane & 3);
                afrag[mt][0] = f2tf32(as[r * PITCH_G + c]);
                afrag[mt][1] = f2tf32(as[(r + 8) * PITCH_G + c]);
                afrag[mt][2] = f2tf32(as[r * PITCH_G + c + 4]);
                afrag[mt][3] = f2tf32(as[(r + 8) * PITCH_G + c + 4]);
            }
            uint32_t bfrag[NT][2];
#pragma unroll
            for (int nt = 0; nt < NT; nt++) {
                int n = nt * 8 + (lane >> 2);
                int c = kk * 8 + (lane & 3);
                bfrag[nt][0] = f2tf32(bs[n * PITCH_G + c]);
                bfrag[nt][1] = f2tf32(bs[n * PITCH_G + c + 4]);
            }
#pragma unroll
            for (int mt = 0; mt < 4; mt++)
#pragma unroll
                for (int nt = 0; nt < NT; nt++)
                    mma_tf32(acc[mt][nt], afrag[mt], bfrag[nt]);
        }
        __syncthreads();
    }

    // Epilogue
#pragma unroll
    for (int mt = 0; mt < 4; mt++) {
#pragma unroll
        for (int nt = 0; nt < NT; nt++) {
            int r0 = bm + wm * 64 + mt * 16 + (lane >> 2);
            int c0 = bn + wn * (BN / 2) + nt * 8 + (lane & 3) * 2;
            float b0 = 0.0f, b1 = 0.0f;
            if (ADD_BIAS) { b0 = __ldg(&bias[c0]); b1 = __ldg(&bias[c0 + 1]); }
            float2 v0 = make_float2(acc[mt][nt][0] + b0, acc[mt][nt][1] + b1);
            float2 v1 = make_float2(acc[mt][nt][2] + b0, acc[mt][nt][3] + b1);
            *(float2*)&out[(size_t)r0 * ldo + c0]       = v0;
            *(float2*)&out[(size_t)(r0 + 8) * ldo + c0] = v1;
        }
    }
}

// ---------------------------------------------------------------------------
// Soft top-k mask: one warp per row of 64 z values.
// Exact 16th-largest |z| (counting duplicates) via 16 max-extractions,
// then z_sparse = z * sigmoid((|z|-thr)/TEMP) * SCALE.
// ---------------------------------------------------------------------------
__global__ void topk_mask_kernel(const float* __restrict__ z,
                                 float* __restrict__ zs, int M)
{
    const int row  = blockIdx.x * 8 + (threadIdx.x >> 5);
    const int lane = threadIdx.x & 31;
    if (row >= M) return;

    float z0 = z[row * R_C + lane];
    float z1 = z[row * R_C + lane + 32];
    float v0 = fabsf(z0), v1 = fabsf(z1);
    bool alive0 = true, alive1 = true;
    float thr = 0.0f;

#pragma unroll 1
    for (int it = 0; it < KSEL_C; it++) {
        float m = fmaxf(alive0 ? v0 : -1.0f, alive1 ? v1 : -1.0f);
#pragma unroll
        for (int off = 16; off; off >>= 1)
            m = fmaxf(m, __shfl_xor_sync(0xffffffffu, m, off));
        thr = m;
        unsigned b = __ballot_sync(0xffffffffu, alive0 && v0 == m);
        if (b) {
            if (lane == (__ffs(b) - 1)) alive0 = false;
        } else {
            unsigned b2 = __ballot_sync(0xffffffffu, alive1 && v1 == m);
            if (lane == (__ffs(b2) - 1)) alive1 = false;
        }
    }

    const float inv_t = 1.0f / TEMP_C;
    float m0 = 1.0f / (1.0f + expf(-(v0 - thr) * inv_t));
    float m1 = 1.0f / (1.0f + expf(-(v1 - thr) * inv_t));
    zs[row * R_C + lane]      = z0 * m0 * SCALE_C;
    zs[row * R_C + lane + 32] = z1 * m1 * SCALE_C;
}

// ---------------------------------------------------------------------------
// Launch
// ---------------------------------------------------------------------------
extern "C" void kernel_launch(void* const* d_in, const int* in_sizes, int n_in,
                              void* d_out, int out_size)
{
    const float* x    = (const float*)d_in[0];   // [M][4096]
    const float* Amat = (const float*)d_in[1];   // [64][4096]
    const float* Bmat = (const float*)d_in[2];   // [4096][64]
    const float* Wmat = (const float*)d_in[3];   // [4096][4096]
    const float* bias = (const float*)d_in[4];   // [4096]
    float* out = (float*)d_out;

    const int M = in_sizes[0] / D_IN_C;          // 8192
    const int N = in_sizes[4];                   // 4096

    float *z_ptr = nullptr, *zs_ptr = nullptr;
    cudaGetSymbolAddress((void**)&z_ptr,  g_z);
    cudaGetSymbolAddress((void**)&zs_ptr, g_zs);

    const int smem_z    = 2 * (BM_G + 64)  * PITCH_G * 4;   // 55296 B
    const int smem_main = 2 * (BM_G + 128) * PITCH_G * 4;   // 73728 B
    cudaFuncSetAttribute(gemm_tf32<64,  false, false>,
                         cudaFuncAttributeMaxDynamicSharedMemorySize, smem_z);
    cudaFuncSetAttribute(gemm_tf32<128, true,  true>,
                         cudaFuncAttributeMaxDynamicSharedMemorySize, smem_main);

    // 1) z = x @ A^T   (M x 64, K = 4096)
    {
        dim3 grid(64 / 64, M / BM_G);
        gemm_tf32<64, false, false><<<grid, 128, smem_z>>>(
            x, D_IN_C, Amat, D_IN_C,
            nullptr, nullptr, nullptr,
            z_ptr, R_C,
            D_IN_C / BK_G, D_IN_C / BK_G);
    }

    // 2) soft top-k mask -> z_sparse (scaled)
    topk_mask_kernel<<<M / 8, 256>>>(z_ptr, zs_ptr, M);

    // 3) out = x @ W^T + bias + z_sparse @ B^T   (K-extension fusion: 4096 + 64)
    {
        dim3 grid(N / 128, M / BM_G);
        gemm_tf32<128, true, true><<<grid, 128, smem_main>>>(
            x, D_IN_C, Wmat, D_IN_C,
            zs_ptr, Bmat, bias,
            out, N,
            D_IN_C / BK_G, D_IN_C / BK_G + R_C / BK_G);
    }
}